// round 9
// baseline (speedup 1.0000x reference)
#include <cuda_runtime.h>

#define NNODES 50000
#define DD 16
#define BB 32
#define NPAIR 16
#define NDRVN 500
#define FEAT 5
#define NMID 5

typedef unsigned long long u64;

// State buffers
__device__ float g_zA[NNODES * BB];
__device__ float g_zB[NNODES * BB];
__device__ float g_z3[NDRVN * DD * BB];
__device__ float g_zf[NDRVN * BB];

// ---------------------------------------------------------------------------
// Packed f32x2 helpers
// ---------------------------------------------------------------------------
__device__ __forceinline__ u64 ffma2(u64 a, u64 b, u64 c) {
    u64 d;
    asm("fma.rn.f32x2 %0, %1, %2, %3;" : "=l"(d) : "l"(a), "l"(b), "l"(c));
    return d;
}
__device__ __forceinline__ u64 add2(u64 a, u64 b) {
    u64 d;
    asm("add.rn.f32x2 %0, %1, %2;" : "=l"(d) : "l"(a), "l"(b));
    return d;
}
__device__ __forceinline__ u64 mul2(u64 a, u64 b) {
    u64 d;
    asm("mul.rn.f32x2 %0, %1, %2;" : "=l"(d) : "l"(a), "l"(b));
    return d;
}
__device__ __forceinline__ u64 relu2(u64 x) {
    unsigned lo, hi;
    asm("mov.b64 {%0,%1}, %2;" : "=r"(lo), "=r"(hi) : "l"(x));
    float a = fmaxf(__uint_as_float(lo), 0.0f);
    float b = fmaxf(__uint_as_float(hi), 0.0f);
    u64 r;
    asm("mov.b64 %0, {%1,%2};" : "=l"(r) : "r"(__float_as_uint(a)), "r"(__float_as_uint(b)));
    return r;
}
__device__ __forceinline__ u64 pack2(float w) {
    u64 r;
    unsigned u = __float_as_uint(w);
    asm("mov.b64 %0, {%1,%1};" : "=l"(r) : "r"(u));
    return r;
}

// ---------------------------------------------------------------------------
// Transpose x [B, N] -> g_zA [N, B]
// ---------------------------------------------------------------------------
__global__ void transpose_kernel(const float* __restrict__ x) {
    __shared__ float tile[32][33];
    int n0 = blockIdx.x * 32;
    int tx = threadIdx.x, ty = threadIdx.y;
    int n = n0 + tx;
    if (n < NNODES) tile[ty][tx] = x[ty * NNODES + n];
    __syncthreads();
    int n2 = n0 + ty;
    if (n2 < NNODES) g_zA[n2 * BB + tx] = tile[tx][ty];
}

// ===========================================================================
// FULL PASS (FFMA2 packed), staged gather to keep live regs under 170
// ===========================================================================
template <int WIN>
__device__ __forceinline__ void mid_layer_p(u64 (&h)[FEAT][DD - 2],
                                            const u64* __restrict__ sw,
                                            const u64* __restrict__ sb) {
    #pragma unroll
    for (int w = 0; w < WIN - 2; w++) {
        u64 tmp[FEAT];
        #pragma unroll
        for (int co = 0; co < FEAT; co++) {
            u64 a = sb[co];
            #pragma unroll
            for (int ci = 0; ci < FEAT; ci++) {
                a = ffma2(sw[(co * FEAT + ci) * 3 + 0], h[ci][w + 0], a);
                a = ffma2(sw[(co * FEAT + ci) * 3 + 1], h[ci][w + 1], a);
                a = ffma2(sw[(co * FEAT + ci) * 3 + 2], h[ci][w + 2], a);
            }
            tmp[co] = relu2(a);
        }
        #pragma unroll
        for (int co = 0; co < FEAT; co++) h[co][w] = tmp[co];
    }
}

template <int SRC>   // SRC=0: g_zA -> g_zB;  SRC=1: g_zB -> g_zA
__global__ void __launch_bounds__(128, 3)
pass_full(const int* __restrict__ nbr,
          const float* __restrict__ w_first, const float* __restrict__ b_first,
          const float* __restrict__ w_mid,   const float* __restrict__ b_mid,
          const float* __restrict__ w_last,  const float* __restrict__ b_last) {
    __shared__ u64 swf[FEAT * 3];
    __shared__ u64 sbf[FEAT];
    __shared__ u64 swm[NMID * FEAT * FEAT * 3];
    __shared__ u64 sbm[NMID * FEAT];
    __shared__ u64 swl[FEAT * 3];
    __shared__ u64 sbl[1];

    int t = threadIdx.x;
    if (t < FEAT * 3) swf[t] = pack2(w_first[t]);
    if (t < FEAT) sbf[t] = pack2(b_first[t]);
    for (int i = t; i < NMID * FEAT * FEAT * 3; i += blockDim.x) swm[i] = pack2(w_mid[i]);
    if (t < NMID * FEAT) sbm[t] = pack2(b_mid[t]);
    if (t < FEAT * 3) swl[t] = pack2(w_last[t]);
    if (t == 0) sbl[0] = pack2(b_last[0]);
    __syncthreads();

    const u64* __restrict__ zin = SRC == 0 ? (const u64*)g_zA : (const u64*)g_zB;
    u64* __restrict__ zout      = SRC == 0 ? (u64*)g_zB : (u64*)g_zA;

    unsigned gid = blockIdx.x * blockDim.x + threadIdx.x;
    if (gid >= (unsigned)NNODES * NPAIR) return;
    int n = gid >> 4;
    int p = gid & 15;

    const int* nb = nbr + n * DD;
    u64 h[FEAT][DD - 2];

    // first-conv weights hoisted once (15 + 5 values)
    u64 wf[FEAT * 3], bf[FEAT];
    #pragma unroll
    for (int i = 0; i < FEAT * 3; i++) wf[i] = swf[i];
    #pragma unroll
    for (int c = 0; c < FEAT; c++) bf[c] = sbf[c];

    // ---- stage 1: gather v[0..7], compute output positions 0..5 ----
    u64 v[DD];
    #pragma unroll
    for (int d = 0; d < 8; d++) {
        int idx = __ldg(&nb[d]);
        v[d] = __ldg(&zin[idx * NPAIR + p]);
    }
    #pragma unroll
    for (int c = 0; c < FEAT; c++) {
        #pragma unroll
        for (int w = 0; w < 6; w++) {
            u64 a = bf[c];
            a = ffma2(wf[c * 3 + 0], v[w + 0], a);
            a = ffma2(wf[c * 3 + 1], v[w + 1], a);
            a = ffma2(wf[c * 3 + 2], v[w + 2], a);
            h[c][w] = relu2(a);
        }
    }
    asm volatile("" ::: "memory");   // keep second-half loads below the computes

    // ---- stage 2: gather v[8..15], compute output positions 6..13 ----
    #pragma unroll
    for (int d = 8; d < DD; d++) {
        int idx = __ldg(&nb[d]);
        v[d] = __ldg(&zin[idx * NPAIR + p]);
    }
    #pragma unroll
    for (int c = 0; c < FEAT; c++) {
        #pragma unroll
        for (int w = 6; w < 14; w++) {
            u64 a = bf[c];
            a = ffma2(wf[c * 3 + 0], v[w + 0], a);
            a = ffma2(wf[c * 3 + 1], v[w + 1], a);
            a = ffma2(wf[c * 3 + 2], v[w + 2], a);
            h[c][w] = relu2(a);
        }
    }

    mid_layer_p<14>(h, swm + 0 * FEAT * FEAT * 3, sbm + 0 * FEAT);
    mid_layer_p<12>(h, swm + 1 * FEAT * FEAT * 3, sbm + 1 * FEAT);
    mid_layer_p<10>(h, swm + 2 * FEAT * FEAT * 3, sbm + 2 * FEAT);
    mid_layer_p<8>(h,  swm + 3 * FEAT * FEAT * 3, sbm + 3 * FEAT);
    mid_layer_p<6>(h,  swm + 4 * FEAT * FEAT * 3, sbm + 4 * FEAT);

    u64 o[2];
    #pragma unroll
    for (int w = 0; w < 2; w++) {
        u64 a = sbl[0];
        #pragma unroll
        for (int ci = 0; ci < FEAT; ci++) {
            a = ffma2(swl[ci * 3 + 0], h[ci][w + 0], a);
            a = ffma2(swl[ci * 3 + 1], h[ci][w + 1], a);
            a = ffma2(swl[ci * 3 + 2], h[ci][w + 2], a);
        }
        o[w] = relu2(a);
    }
    zout[n * NPAIR + p] = mul2(add2(o[0], o[1]), pack2(0.5f));
}

// ===========================================================================
// SCALAR conv body — lite passes
// ===========================================================================
struct SW {
    float swf[FEAT * 3]; float sbf[FEAT];
    float swm[NMID * FEAT * FEAT * 3]; float sbm[NMID * FEAT];
    float swl[FEAT * 3]; float sbl[1];
};

__device__ __forceinline__ void load_weights(SW* s,
        const float* __restrict__ w_first, const float* __restrict__ b_first,
        const float* __restrict__ w_mid,   const float* __restrict__ b_mid,
        const float* __restrict__ w_last,  const float* __restrict__ b_last,
        int t, int bs) {
    if (t < FEAT * 3) s->swf[t] = w_first[t];
    if (t < FEAT) s->sbf[t] = b_first[t];
    for (int i = t; i < NMID * FEAT * FEAT * 3; i += bs) s->swm[i] = w_mid[i];
    if (t < NMID * FEAT) s->sbm[t] = b_mid[t];
    if (t < FEAT * 3) s->swl[t] = w_last[t];
    if (t == 0) s->sbl[0] = b_last[0];
}

template <int WIN, int AW, int BW>
__device__ __forceinline__ void mid_layer_s(const float (&hin)[FEAT][AW],
                                            float (&hout)[FEAT][BW],
                                            const float* __restrict__ sw,
                                            const float* __restrict__ sb) {
    #pragma unroll
    for (int co = 0; co < FEAT; co++) {
        float wr[FEAT * 3];
        #pragma unroll
        for (int i = 0; i < FEAT * 3; i++) wr[i] = sw[(co * FEAT) * 3 + i];
        float bias = sb[co];
        #pragma unroll
        for (int w = 0; w < WIN - 2; w++) {
            float a = bias;
            #pragma unroll
            for (int ci = 0; ci < FEAT; ci++) {
                a = fmaf(wr[ci * 3 + 0], hin[ci][w + 0], a);
                a = fmaf(wr[ci * 3 + 1], hin[ci][w + 1], a);
                a = fmaf(wr[ci * 3 + 2], hin[ci][w + 2], a);
            }
            hout[co][w] = fmaxf(a, 0.0f);
        }
    }
}

__device__ __forceinline__ float conv_stack(const float (&v)[DD], const SW* s) {
    float hA[FEAT][14];
    #pragma unroll
    for (int c = 0; c < FEAT; c++) {
        float w0 = s->swf[c * 3 + 0], w1 = s->swf[c * 3 + 1], w2 = s->swf[c * 3 + 2];
        float bias = s->sbf[c];
        #pragma unroll
        for (int w = 0; w < 14; w++) {
            float a = bias;
            a = fmaf(w0, v[w + 0], a);
            a = fmaf(w1, v[w + 1], a);
            a = fmaf(w2, v[w + 2], a);
            hA[c][w] = fmaxf(a, 0.0f);
        }
    }
    float hB[FEAT][12];
    mid_layer_s<14>(hA, hB, s->swm + 0 * FEAT * FEAT * 3, s->sbm + 0 * FEAT);
    mid_layer_s<12>(hB, hA, s->swm + 1 * FEAT * FEAT * 3, s->sbm + 1 * FEAT);
    mid_layer_s<10>(hA, hB, s->swm + 2 * FEAT * FEAT * 3, s->sbm + 2 * FEAT);
    mid_layer_s<8>(hB, hA,  s->swm + 3 * FEAT * FEAT * 3, s->sbm + 3 * FEAT);
    mid_layer_s<6>(hA, hB,  s->swm + 4 * FEAT * FEAT * 3, s->sbm + 4 * FEAT);

    float o[2];
    #pragma unroll
    for (int w = 0; w < 2; w++) {
        float a = s->sbl[0];
        #pragma unroll
        for (int ci = 0; ci < FEAT; ci++) {
            a = fmaf(s->swl[ci * 3 + 0], hB[ci][w + 0], a);
            a = fmaf(s->swl[ci * 3 + 1], hB[ci][w + 1], a);
            a = fmaf(s->swl[ci * 3 + 2], hB[ci][w + 2], a);
        }
        o[w] = fmaxf(a, 0.0f);
    }
    return 0.5f * (o[0] + o[1]);
}

// ---------------------------------------------------------------------------
// Pass 3 (lite): z3 at the 500x16 driver-neighbor slots, reads g_zA (z2)
// ---------------------------------------------------------------------------
__global__ void __launch_bounds__(128)
pass3_lite(const int* __restrict__ nbr, const int* __restrict__ drivers,
           const float* __restrict__ w_first, const float* __restrict__ b_first,
           const float* __restrict__ w_mid,   const float* __restrict__ b_mid,
           const float* __restrict__ w_last,  const float* __restrict__ b_last) {
    __shared__ SW s;
    load_weights(&s, w_first, b_first, w_mid, b_mid, w_last, b_last,
                 threadIdx.x, blockDim.x);
    __syncthreads();

    unsigned gid = blockIdx.x * blockDim.x + threadIdx.x;
    if (gid >= (unsigned)NDRVN * DD * BB) return;
    int job = gid >> 5;
    int b = gid & 31;

    int d = job >> 4;
    int j = job & 15;
    int m = __ldg(&nbr[__ldg(&drivers[d]) * DD + j]);

    float v[DD];
    const int* nb = nbr + m * DD;
    #pragma unroll
    for (int k = 0; k < DD; k++) {
        int idx = __ldg(&nb[k]);
        v[k] = __ldg(&g_zA[idx * BB + b]);
    }
    g_z3[job * BB + b] = conv_stack(v, &s);
}

// ---------------------------------------------------------------------------
// Pass 4 (lite): only the 500 driver nodes, inputs direct from g_z3
// ---------------------------------------------------------------------------
__global__ void __launch_bounds__(128)
pass4_lite(const float* __restrict__ w_first, const float* __restrict__ b_first,
           const float* __restrict__ w_mid,   const float* __restrict__ b_mid,
           const float* __restrict__ w_last,  const float* __restrict__ b_last) {
    __shared__ SW s;
    load_weights(&s, w_first, b_first, w_mid, b_mid, w_last, b_last,
                 threadIdx.x, blockDim.x);
    __syncthreads();

    unsigned gid = blockIdx.x * blockDim.x + threadIdx.x;
    if (gid >= (unsigned)NDRVN * BB) return;
    int d = gid >> 5;
    int b = gid & 31;

    float v[DD];
    #pragma unroll
    for (int k = 0; k < DD; k++)
        v[k] = __ldg(&g_z3[(d * DD + k) * BB + b]);
    g_zf[d * BB + b] = conv_stack(v, &s);
}

// ---------------------------------------------------------------------------
__global__ void zero_kernel(float4* __restrict__ out, int n4) {
    int i = blockIdx.x * blockDim.x + threadIdx.x;
    if (i < n4) out[i] = make_float4(0.f, 0.f, 0.f, 0.f);
}

// ---------------------------------------------------------------------------
// Masked softmax over driver columns; reads g_zf [500][B]
// ---------------------------------------------------------------------------
__global__ void softmax_kernel(const int* __restrict__ drivers,
                               float* __restrict__ out) {
    __shared__ float red[512];
    int b = blockIdx.x;
    int t = threadIdx.x;

    float myv = 0.0f;
    int drv = -1;
    float mval = -INFINITY;
    if (t < NDRVN) {
        drv = drivers[t];
        myv = g_zf[t * BB + b];
        mval = myv;
    }
    red[t] = mval;
    __syncthreads();
    #pragma unroll
    for (int s = 256; s > 0; s >>= 1) {
        if (t < s) red[t] = fmaxf(red[t], red[t + s]);
        __syncthreads();
    }
    float m = fmaxf(red[0], 0.0f);
    __syncthreads();

    float e = (t < NDRVN) ? expf(myv - m) : 0.0f;
    red[t] = e;
    __syncthreads();
    #pragma unroll
    for (int s = 256; s > 0; s >>= 1) {
        if (t < s) red[t] += red[t + s];
        __syncthreads();
    }
    float Z = red[0] + (float)(NNODES - NDRVN) * expf(-m);

    if (t < NDRVN) out[b * NNODES + drv] = e / Z;
}

// ---------------------------------------------------------------------------
extern "C" void kernel_launch(void* const* d_in, const int* in_sizes, int n_in,
                              void* d_out, int out_size) {
    const float* x       = (const float*)d_in[0];
    const int*   nbr     = (const int*)  d_in[1];
    const int*   drivers = (const int*)  d_in[2];
    const float* w_first = (const float*)d_in[4];
    const float* b_first = (const float*)d_in[5];
    const float* w_mid   = (const float*)d_in[6];
    const float* b_mid   = (const float*)d_in[7];
    const float* w_last  = (const float*)d_in[8];
    const float* b_last  = (const float*)d_in[9];
    float* out = (float*)d_out;

    // zero d_out first (independent of everything downstream)
    int n4 = NNODES * BB / 4;
    zero_kernel<<<(n4 + 255) / 256, 256>>>((float4*)out, n4);

    transpose_kernel<<<(NNODES + 31) / 32, dim3(32, 32)>>>(x);

    const int blk = 128;
    const int grid_full = (NNODES * NPAIR + blk - 1) / blk;

    pass_full<0><<<grid_full, blk>>>(nbr, w_first, b_first, w_mid, b_mid, w_last, b_last);
    pass_full<1><<<grid_full, blk>>>(nbr, w_first, b_first, w_mid, b_mid, w_last, b_last);

    const int grid3 = (NDRVN * DD * BB + blk - 1) / blk;
    pass3_lite<<<grid3, blk>>>(nbr, drivers, w_first, b_first, w_mid, b_mid, w_last, b_last);

    const int grid4 = (NDRVN * BB + blk - 1) / blk;
    pass4_lite<<<grid4, blk>>>(w_first, b_first, w_mid, b_mid, w_last, b_last);

    softmax_kernel<<<BB, 512>>>(drivers, out);
}

// round 10
// speedup vs baseline: 1.3555x; 1.3555x over previous
#include <cuda_runtime.h>

#define NNODES 50000
#define DD 16
#define BB 32
#define NPAIR 16
#define NDRVN 500
#define FEAT 5
#define NMID 5

typedef unsigned long long u64;

// State buffers
__device__ float g_zA[NNODES * BB];
__device__ float g_zB[NNODES * BB];
__device__ float g_z3[NDRVN * DD * BB];
__device__ float g_zf[NDRVN * BB];

// Weights in constant memory (filled by async D2D copies in kernel_launch)
__constant__ float c_wf[FEAT * 3];
__constant__ float c_bf[FEAT];
__constant__ float c_wm[NMID * FEAT * FEAT * 3];
__constant__ float c_bm[NMID * FEAT];
__constant__ float c_wl[FEAT * 3];
__constant__ float c_bl[1];

// ---------------------------------------------------------------------------
// Packed f32x2 helpers
// ---------------------------------------------------------------------------
__device__ __forceinline__ u64 ffma2(u64 a, u64 b, u64 c) {
    u64 d;
    asm("fma.rn.f32x2 %0, %1, %2, %3;" : "=l"(d) : "l"(a), "l"(b), "l"(c));
    return d;
}
__device__ __forceinline__ u64 add2(u64 a, u64 b) {
    u64 d;
    asm("add.rn.f32x2 %0, %1, %2;" : "=l"(d) : "l"(a), "l"(b));
    return d;
}
__device__ __forceinline__ u64 relu2(u64 x) {
    unsigned lo, hi;
    asm("mov.b64 {%0,%1}, %2;" : "=r"(lo), "=r"(hi) : "l"(x));
    float a = fmaxf(__uint_as_float(lo), 0.0f);
    float b = fmaxf(__uint_as_float(hi), 0.0f);
    u64 r;
    asm("mov.b64 %0, {%1,%2};" : "=l"(r) : "r"(__float_as_uint(a)), "r"(__float_as_uint(b)));
    return r;
}
__device__ __forceinline__ u64 pack2(float w) {
    u64 r;
    unsigned u = __float_as_uint(w);
    asm("mov.b64 %0, {%1,%1};" : "=l"(r) : "r"(u));
    return r;
}

// ---------------------------------------------------------------------------
// Transpose x [B, N] -> g_zA [N, B]
// ---------------------------------------------------------------------------
__global__ void transpose_kernel(const float* __restrict__ x) {
    __shared__ float tile[32][33];
    int n0 = blockIdx.x * 32;
    int tx = threadIdx.x, ty = threadIdx.y;
    int n = n0 + tx;
    if (n < NNODES) tile[ty][tx] = x[ty * NNODES + n];
    __syncthreads();
    int n2 = n0 + ty;
    if (n2 < NNODES) g_zA[n2 * BB + tx] = tile[tx][ty];
}

// ===========================================================================
// VARIANT A: scalar body, weights from __constant__ (UR-operand FFMA bet)
// warp = node, lane = batch. zA -> zB.
// ===========================================================================
template <int WIN, int AW, int BW>
__device__ __forceinline__ void mid_layer_c(const float (&hin)[FEAT][AW],
                                            float (&hout)[FEAT][BW],
                                            int L) {
    const float* wbase = c_wm + L * FEAT * FEAT * 3;
    const float* bbase = c_bm + L * FEAT;
    #pragma unroll
    for (int co = 0; co < FEAT; co++) {
        float bias = bbase[co];
        #pragma unroll
        for (int w = 0; w < WIN - 2; w++) {
            float a = bias;
            #pragma unroll
            for (int ci = 0; ci < FEAT; ci++) {
                a = fmaf(wbase[(co * FEAT + ci) * 3 + 0], hin[ci][w + 0], a);
                a = fmaf(wbase[(co * FEAT + ci) * 3 + 1], hin[ci][w + 1], a);
                a = fmaf(wbase[(co * FEAT + ci) * 3 + 2], hin[ci][w + 2], a);
            }
            hout[co][w] = fmaxf(a, 0.0f);
        }
    }
}

__global__ void __launch_bounds__(128)
pass_const(const int* __restrict__ nbr) {
    unsigned gid = blockIdx.x * blockDim.x + threadIdx.x;
    if (gid >= (unsigned)NNODES * BB) return;
    int n = gid >> 5;
    int b = gid & 31;

    float v[DD];
    const int* nb = nbr + n * DD;
    #pragma unroll
    for (int d = 0; d < DD; d++) {
        int idx = __ldg(&nb[d]);
        v[d] = __ldg(&g_zA[idx * BB + b]);
    }

    float hA[FEAT][14];
    #pragma unroll
    for (int c = 0; c < FEAT; c++) {
        float bias = c_bf[c];
        #pragma unroll
        for (int w = 0; w < 14; w++) {
            float a = bias;
            a = fmaf(c_wf[c * 3 + 0], v[w + 0], a);
            a = fmaf(c_wf[c * 3 + 1], v[w + 1], a);
            a = fmaf(c_wf[c * 3 + 2], v[w + 2], a);
            hA[c][w] = fmaxf(a, 0.0f);
        }
    }

    float hB[FEAT][12];
    mid_layer_c<14>(hA, hB, 0);
    mid_layer_c<12>(hB, hA, 1);
    mid_layer_c<10>(hA, hB, 2);
    mid_layer_c<8>(hB, hA, 3);
    mid_layer_c<6>(hA, hB, 4);

    float o[2];
    #pragma unroll
    for (int w = 0; w < 2; w++) {
        float a = c_bl[0];
        #pragma unroll
        for (int ci = 0; ci < FEAT; ci++) {
            a = fmaf(c_wl[ci * 3 + 0], hB[ci][w + 0], a);
            a = fmaf(c_wl[ci * 3 + 1], hB[ci][w + 1], a);
            a = fmaf(c_wl[ci * 3 + 2], hB[ci][w + 2], a);
        }
        o[w] = fmaxf(a, 0.0f);
    }
    g_zB[n * BB + b] = 0.5f * (o[0] + o[1]);
}

// ===========================================================================
// VARIANT B: exact R3 packed body (proven 234us). zB -> zA.
// ===========================================================================
template <int WIN>
__device__ __forceinline__ void mid_layer_p(u64 (&h)[FEAT][DD - 2],
                                            const u64* __restrict__ sw,
                                            const u64* __restrict__ sb) {
    #pragma unroll
    for (int w = 0; w < WIN - 2; w++) {
        u64 tmp[FEAT];
        #pragma unroll
        for (int co = 0; co < FEAT; co++) {
            u64 a = sb[co];
            #pragma unroll
            for (int ci = 0; ci < FEAT; ci++) {
                a = ffma2(sw[(co * FEAT + ci) * 3 + 0], h[ci][w + 0], a);
                a = ffma2(sw[(co * FEAT + ci) * 3 + 1], h[ci][w + 1], a);
                a = ffma2(sw[(co * FEAT + ci) * 3 + 2], h[ci][w + 2], a);
            }
            tmp[co] = relu2(a);
        }
        #pragma unroll
        for (int co = 0; co < FEAT; co++) h[co][w] = tmp[co];
    }
}

__global__ void __launch_bounds__(128)
pass_packed(const int* __restrict__ nbr,
            const float* __restrict__ w_first, const float* __restrict__ b_first,
            const float* __restrict__ w_mid,   const float* __restrict__ b_mid,
            const float* __restrict__ w_last,  const float* __restrict__ b_last) {
    __shared__ u64 swf[FEAT * 3];
    __shared__ u64 sbf[FEAT];
    __shared__ u64 swm[NMID * FEAT * FEAT * 3];
    __shared__ u64 sbm[NMID * FEAT];
    __shared__ u64 swl[FEAT * 3];
    __shared__ u64 sbl[1];

    int t = threadIdx.x;
    if (t < FEAT * 3) swf[t] = pack2(w_first[t]);
    if (t < FEAT) sbf[t] = pack2(b_first[t]);
    for (int i = t; i < NMID * FEAT * FEAT * 3; i += blockDim.x) swm[i] = pack2(w_mid[i]);
    if (t < NMID * FEAT) sbm[t] = pack2(b_mid[t]);
    if (t < FEAT * 3) swl[t] = pack2(w_last[t]);
    if (t == 0) sbl[0] = pack2(b_last[0]);
    __syncthreads();

    const u64* __restrict__ zin = (const u64*)g_zB;
    u64* __restrict__ zout      = (u64*)g_zA;

    unsigned gid = blockIdx.x * blockDim.x + threadIdx.x;
    if (gid >= (unsigned)NNODES * NPAIR) return;
    int n = gid >> 4;
    int p = gid & 15;

    u64 v[DD];
    const int* nb = nbr + n * DD;
    #pragma unroll
    for (int d = 0; d < DD; d++) {
        int idx = __ldg(&nb[d]);
        v[d] = __ldg(&zin[idx * NPAIR + p]);
    }

    u64 h[FEAT][DD - 2];
    #pragma unroll
    for (int c = 0; c < FEAT; c++) {
        #pragma unroll
        for (int w = 0; w < DD - 2; w++) {
            u64 a = sbf[c];
            a = ffma2(swf[c * 3 + 0], v[w + 0], a);
            a = ffma2(swf[c * 3 + 1], v[w + 1], a);
            a = ffma2(swf[c * 3 + 2], v[w + 2], a);
            h[c][w] = relu2(a);
        }
    }

    mid_layer_p<14>(h, swm + 0 * FEAT * FEAT * 3, sbm + 0 * FEAT);
    mid_layer_p<12>(h, swm + 1 * FEAT * FEAT * 3, sbm + 1 * FEAT);
    mid_layer_p<10>(h, swm + 2 * FEAT * FEAT * 3, sbm + 2 * FEAT);
    mid_layer_p<8>(h,  swm + 3 * FEAT * FEAT * 3, sbm + 3 * FEAT);
    mid_layer_p<6>(h,  swm + 4 * FEAT * FEAT * 3, sbm + 4 * FEAT);

    u64 o[2];
    #pragma unroll
    for (int w = 0; w < 2; w++) {
        u64 a = sbl[0];
        #pragma unroll
        for (int ci = 0; ci < FEAT; ci++) {
            a = ffma2(swl[ci * 3 + 0], h[ci][w + 0], a);
            a = ffma2(swl[ci * 3 + 1], h[ci][w + 1], a);
            a = ffma2(swl[ci * 3 + 2], h[ci][w + 2], a);
        }
        o[w] = relu2(a);
    }
    u64 s = add2(o[0], o[1]);
    zout[n * NPAIR + p] = ffma2(s, pack2(0.5f), pack2(0.0f));
}

// ===========================================================================
// SCALAR conv body from shared — lite passes (proven R7)
// ===========================================================================
struct SW {
    float swf[FEAT * 3]; float sbf[FEAT];
    float swm[NMID * FEAT * FEAT * 3]; float sbm[NMID * FEAT];
    float swl[FEAT * 3]; float sbl[1];
};

__device__ __forceinline__ void load_weights(SW* s,
        const float* __restrict__ w_first, const float* __restrict__ b_first,
        const float* __restrict__ w_mid,   const float* __restrict__ b_mid,
        const float* __restrict__ w_last,  const float* __restrict__ b_last,
        int t, int bs) {
    if (t < FEAT * 3) s->swf[t] = w_first[t];
    if (t < FEAT) s->sbf[t] = b_first[t];
    for (int i = t; i < NMID * FEAT * FEAT * 3; i += bs) s->swm[i] = w_mid[i];
    if (t < NMID * FEAT) s->sbm[t] = b_mid[t];
    if (t < FEAT * 3) s->swl[t] = w_last[t];
    if (t == 0) s->sbl[0] = b_last[0];
}

template <int WIN, int AW, int BW>
__device__ __forceinline__ void mid_layer_s(const float (&hin)[FEAT][AW],
                                            float (&hout)[FEAT][BW],
                                            const float* __restrict__ sw,
                                            const float* __restrict__ sb) {
    #pragma unroll
    for (int co = 0; co < FEAT; co++) {
        float wr[FEAT * 3];
        #pragma unroll
        for (int i = 0; i < FEAT * 3; i++) wr[i] = sw[(co * FEAT) * 3 + i];
        float bias = sb[co];
        #pragma unroll
        for (int w = 0; w < WIN - 2; w++) {
            float a = bias;
            #pragma unroll
            for (int ci = 0; ci < FEAT; ci++) {
                a = fmaf(wr[ci * 3 + 0], hin[ci][w + 0], a);
                a = fmaf(wr[ci * 3 + 1], hin[ci][w + 1], a);
                a = fmaf(wr[ci * 3 + 2], hin[ci][w + 2], a);
            }
            hout[co][w] = fmaxf(a, 0.0f);
        }
    }
}

__device__ __forceinline__ float conv_stack(const float (&v)[DD], const SW* s) {
    float hA[FEAT][14];
    #pragma unroll
    for (int c = 0; c < FEAT; c++) {
        float w0 = s->swf[c * 3 + 0], w1 = s->swf[c * 3 + 1], w2 = s->swf[c * 3 + 2];
        float bias = s->sbf[c];
        #pragma unroll
        for (int w = 0; w < 14; w++) {
            float a = bias;
            a = fmaf(w0, v[w + 0], a);
            a = fmaf(w1, v[w + 1], a);
            a = fmaf(w2, v[w + 2], a);
            hA[c][w] = fmaxf(a, 0.0f);
        }
    }
    float hB[FEAT][12];
    mid_layer_s<14>(hA, hB, s->swm + 0 * FEAT * FEAT * 3, s->sbm + 0 * FEAT);
    mid_layer_s<12>(hB, hA, s->swm + 1 * FEAT * FEAT * 3, s->sbm + 1 * FEAT);
    mid_layer_s<10>(hA, hB, s->swm + 2 * FEAT * FEAT * 3, s->sbm + 2 * FEAT);
    mid_layer_s<8>(hB, hA,  s->swm + 3 * FEAT * FEAT * 3, s->sbm + 3 * FEAT);
    mid_layer_s<6>(hA, hB,  s->swm + 4 * FEAT * FEAT * 3, s->sbm + 4 * FEAT);

    float o[2];
    #pragma unroll
    for (int w = 0; w < 2; w++) {
        float a = s->sbl[0];
        #pragma unroll
        for (int ci = 0; ci < FEAT; ci++) {
            a = fmaf(s->swl[ci * 3 + 0], hB[ci][w + 0], a);
            a = fmaf(s->swl[ci * 3 + 1], hB[ci][w + 1], a);
            a = fmaf(s->swl[ci * 3 + 2], hB[ci][w + 2], a);
        }
        o[w] = fmaxf(a, 0.0f);
    }
    return 0.5f * (o[0] + o[1]);
}

// ---------------------------------------------------------------------------
// Pass 3 (lite): z3 at the 500x16 driver-neighbor slots, reads g_zA (z2)
// ---------------------------------------------------------------------------
__global__ void __launch_bounds__(128)
pass3_lite(const int* __restrict__ nbr, const int* __restrict__ drivers,
           const float* __restrict__ w_first, const float* __restrict__ b_first,
           const float* __restrict__ w_mid,   const float* __restrict__ b_mid,
           const float* __restrict__ w_last,  const float* __restrict__ b_last) {
    __shared__ SW s;
    load_weights(&s, w_first, b_first, w_mid, b_mid, w_last, b_last,
                 threadIdx.x, blockDim.x);
    __syncthreads();

    unsigned gid = blockIdx.x * blockDim.x + threadIdx.x;
    if (gid >= (unsigned)NDRVN * DD * BB) return;
    int job = gid >> 5;
    int b = gid & 31;

    int d = job >> 4;
    int j = job & 15;
    int m = __ldg(&nbr[__ldg(&drivers[d]) * DD + j]);

    float v[DD];
    const int* nb = nbr + m * DD;
    #pragma unroll
    for (int k = 0; k < DD; k++) {
        int idx = __ldg(&nb[k]);
        v[k] = __ldg(&g_zA[idx * BB + b]);
    }
    g_z3[job * BB + b] = conv_stack(v, &s);
}

// ---------------------------------------------------------------------------
// Pass 4 (lite): only the 500 driver nodes, inputs direct from g_z3
// ---------------------------------------------------------------------------
__global__ void __launch_bounds__(128)
pass4_lite(const float* __restrict__ w_first, const float* __restrict__ b_first,
           const float* __restrict__ w_mid,   const float* __restrict__ b_mid,
           const float* __restrict__ w_last,  const float* __restrict__ b_last) {
    __shared__ SW s;
    load_weights(&s, w_first, b_first, w_mid, b_mid, w_last, b_last,
                 threadIdx.x, blockDim.x);
    __syncthreads();

    unsigned gid = blockIdx.x * blockDim.x + threadIdx.x;
    if (gid >= (unsigned)NDRVN * BB) return;
    int d = gid >> 5;
    int b = gid & 31;

    float v[DD];
    #pragma unroll
    for (int k = 0; k < DD; k++)
        v[k] = __ldg(&g_z3[(d * DD + k) * BB + b]);
    g_zf[d * BB + b] = conv_stack(v, &s);
}

// ---------------------------------------------------------------------------
__global__ void zero_kernel(float4* __restrict__ out, int n4) {
    int i = blockIdx.x * blockDim.x + threadIdx.x;
    if (i < n4) out[i] = make_float4(0.f, 0.f, 0.f, 0.f);
}

// ---------------------------------------------------------------------------
// Masked softmax over driver columns; reads g_zf [500][B]
// ---------------------------------------------------------------------------
__global__ void softmax_kernel(const int* __restrict__ drivers,
                               float* __restrict__ out) {
    __shared__ float red[512];
    int b = blockIdx.x;
    int t = threadIdx.x;

    float myv = 0.0f;
    int drv = -1;
    float mval = -INFINITY;
    if (t < NDRVN) {
        drv = drivers[t];
        myv = g_zf[t * BB + b];
        mval = myv;
    }
    red[t] = mval;
    __syncthreads();
    #pragma unroll
    for (int s = 256; s > 0; s >>= 1) {
        if (t < s) red[t] = fmaxf(red[t], red[t + s]);
        __syncthreads();
    }
    float m = fmaxf(red[0], 0.0f);
    __syncthreads();

    float e = (t < NDRVN) ? expf(myv - m) : 0.0f;
    red[t] = e;
    __syncthreads();
    #pragma unroll
    for (int s = 256; s > 0; s >>= 1) {
        if (t < s) red[t] += red[t + s];
        __syncthreads();
    }
    float Z = red[0] + (float)(NNODES - NDRVN) * expf(-m);

    if (t < NDRVN) out[b * NNODES + drv] = e / Z;
}

// ---------------------------------------------------------------------------
extern "C" void kernel_launch(void* const* d_in, const int* in_sizes, int n_in,
                              void* d_out, int out_size) {
    const float* x       = (const float*)d_in[0];
    const int*   nbr     = (const int*)  d_in[1];
    const int*   drivers = (const int*)  d_in[2];
    const float* w_first = (const float*)d_in[4];
    const float* b_first = (const float*)d_in[5];
    const float* w_mid   = (const float*)d_in[6];
    const float* b_mid   = (const float*)d_in[7];
    const float* w_last  = (const float*)d_in[8];
    const float* b_last  = (const float*)d_in[9];
    float* out = (float*)d_out;

    // Copy weights into __constant__ (graph-capturable D2D memcpy nodes)
    cudaMemcpyToSymbolAsync(c_wf, w_first, FEAT * 3 * sizeof(float), 0, cudaMemcpyDeviceToDevice);
    cudaMemcpyToSymbolAsync(c_bf, b_first, FEAT * sizeof(float), 0, cudaMemcpyDeviceToDevice);
    cudaMemcpyToSymbolAsync(c_wm, w_mid, NMID * FEAT * FEAT * 3 * sizeof(float), 0, cudaMemcpyDeviceToDevice);
    cudaMemcpyToSymbolAsync(c_bm, b_mid, NMID * FEAT * sizeof(float), 0, cudaMemcpyDeviceToDevice);
    cudaMemcpyToSymbolAsync(c_wl, w_last, FEAT * 3 * sizeof(float), 0, cudaMemcpyDeviceToDevice);
    cudaMemcpyToSymbolAsync(c_bl, b_last, sizeof(float), 0, cudaMemcpyDeviceToDevice);

    // zero d_out (independent)
    int n4 = NNODES * BB / 4;
    zero_kernel<<<(n4 + 255) / 256, 256>>>((float4*)out, n4);

    transpose_kernel<<<(NNODES + 31) / 32, dim3(32, 32)>>>(x);

    const int blk = 128;
    const int grid_sc = (NNODES * BB + blk - 1) / blk;      // scalar threads
    const int grid_pk = (NNODES * NPAIR + blk - 1) / blk;   // packed threads

    // Pass 1: constant-weight scalar variant (UR bet).  zA -> zB
    pass_const<<<grid_sc, blk>>>(nbr);
    // Pass 2: proven R3 packed variant.                 zB -> zA
    pass_packed<<<grid_pk, blk>>>(nbr, w_first, b_first, w_mid, b_mid, w_last, b_last);

    const int grid3 = (NDRVN * DD * BB + blk - 1) / blk;
    pass3_lite<<<grid3, blk>>>(nbr, drivers, w_first, b_first, w_mid, b_mid, w_last, b_last);

    const int grid4 = (NDRVN * BB + blk - 1) / blk;
    pass4_lite<<<grid4, blk>>>(w_first, b_first, w_mid, b_mid, w_last, b_last);

    softmax_kernel<<<BB, 512>>>(drivers, out);
}

// round 11
// speedup vs baseline: 1.4330x; 1.0572x over previous
#include <cuda_runtime.h>

#define NNODES 50000
#define DD 16
#define BB 32
#define NDRVN 500
#define FEAT 5
#define NMID 5

// State buffers
__device__ float g_zA[NNODES * BB];
__device__ float g_zB[NNODES * BB];
__device__ float g_z3[NDRVN * DD * BB];
__device__ float g_zf[NDRVN * BB];

// Weights in constant memory (filled by async D2D copies in kernel_launch)
__constant__ float c_wf[FEAT * 3];
__constant__ float c_bf[FEAT];
__constant__ float c_wm[NMID * FEAT * FEAT * 3];
__constant__ float c_bm[NMID * FEAT];
__constant__ float c_wl[FEAT * 3];
__constant__ float c_bl[1];

// ---------------------------------------------------------------------------
// Transpose x [B, N] -> g_zA [N, B]
// ---------------------------------------------------------------------------
__global__ void transpose_kernel(const float* __restrict__ x) {
    __shared__ float tile[32][33];
    int n0 = blockIdx.x * 32;
    int tx = threadIdx.x, ty = threadIdx.y;
    int n = n0 + tx;
    if (n < NNODES) tile[ty][tx] = x[ty * NNODES + n];
    __syncthreads();
    int n2 = n0 + ty;
    if (n2 < NNODES) g_zA[n2 * BB + tx] = tile[tx][ty];
}

// ===========================================================================
// Constant-weight conv stack (proven fastest body, R10)
// ===========================================================================
template <int WIN, int AW, int BW>
__device__ __forceinline__ void mid_layer_c(const float (&hin)[FEAT][AW],
                                            float (&hout)[FEAT][BW],
                                            int L) {
    const float* wbase = c_wm + L * FEAT * FEAT * 3;
    const float* bbase = c_bm + L * FEAT;
    #pragma unroll
    for (int co = 0; co < FEAT; co++) {
        float bias = bbase[co];
        #pragma unroll
        for (int w = 0; w < WIN - 2; w++) {
            float a = bias;
            #pragma unroll
            for (int ci = 0; ci < FEAT; ci++) {
                a = fmaf(wbase[(co * FEAT + ci) * 3 + 0], hin[ci][w + 0], a);
                a = fmaf(wbase[(co * FEAT + ci) * 3 + 1], hin[ci][w + 1], a);
                a = fmaf(wbase[(co * FEAT + ci) * 3 + 2], hin[ci][w + 2], a);
            }
            hout[co][w] = fmaxf(a, 0.0f);
        }
    }
}

__device__ __forceinline__ float conv_stack_c(const float (&v)[DD]) {
    float hA[FEAT][14];
    #pragma unroll
    for (int c = 0; c < FEAT; c++) {
        float bias = c_bf[c];
        #pragma unroll
        for (int w = 0; w < 14; w++) {
            float a = bias;
            a = fmaf(c_wf[c * 3 + 0], v[w + 0], a);
            a = fmaf(c_wf[c * 3 + 1], v[w + 1], a);
            a = fmaf(c_wf[c * 3 + 2], v[w + 2], a);
            hA[c][w] = fmaxf(a, 0.0f);
        }
    }

    float hB[FEAT][12];
    mid_layer_c<14>(hA, hB, 0);
    mid_layer_c<12>(hB, hA, 1);
    mid_layer_c<10>(hA, hB, 2);
    mid_layer_c<8>(hB, hA, 3);
    mid_layer_c<6>(hA, hB, 4);

    float o[2];
    #pragma unroll
    for (int w = 0; w < 2; w++) {
        float a = c_bl[0];
        #pragma unroll
        for (int ci = 0; ci < FEAT; ci++) {
            a = fmaf(c_wl[ci * 3 + 0], hB[ci][w + 0], a);
            a = fmaf(c_wl[ci * 3 + 1], hB[ci][w + 1], a);
            a = fmaf(c_wl[ci * 3 + 2], hB[ci][w + 2], a);
        }
        o[w] = fmaxf(a, 0.0f);
    }
    return 0.5f * (o[0] + o[1]);
}

// ---------------------------------------------------------------------------
// Full pass: warp = node, lane = batch.  SRC=0: zA->zB, SRC=1: zB->zA
// ---------------------------------------------------------------------------
template <int SRC>
__global__ void __launch_bounds__(128)
pass_const(const int* __restrict__ nbr) {
    const float* __restrict__ zin = SRC == 0 ? g_zA : g_zB;
    float* __restrict__ zout      = SRC == 0 ? g_zB : g_zA;

    unsigned gid = blockIdx.x * blockDim.x + threadIdx.x;
    if (gid >= (unsigned)NNODES * BB) return;
    int n = gid >> 5;
    int b = gid & 31;

    float v[DD];
    const int* nb = nbr + n * DD;
    #pragma unroll
    for (int d = 0; d < DD; d++) {
        int idx = __ldg(&nb[d]);
        v[d] = __ldg(&zin[idx * BB + b]);
    }
    zout[n * BB + b] = conv_stack_c(v);
}

// ---------------------------------------------------------------------------
// Pass 3 (lite): z3 at the 500x16 driver-neighbor slots, reads g_zA (z2)
// ---------------------------------------------------------------------------
__global__ void __launch_bounds__(128)
pass3_lite(const int* __restrict__ nbr, const int* __restrict__ drivers) {
    unsigned gid = blockIdx.x * blockDim.x + threadIdx.x;
    if (gid >= (unsigned)NDRVN * DD * BB) return;
    int job = gid >> 5;
    int b = gid & 31;

    int d = job >> 4;
    int j = job & 15;
    int m = __ldg(&nbr[__ldg(&drivers[d]) * DD + j]);

    float v[DD];
    const int* nb = nbr + m * DD;
    #pragma unroll
    for (int k = 0; k < DD; k++) {
        int idx = __ldg(&nb[k]);
        v[k] = __ldg(&g_zA[idx * BB + b]);
    }
    g_z3[job * BB + b] = conv_stack_c(v);
}

// ---------------------------------------------------------------------------
// Pass 4 (lite): only the 500 driver nodes, inputs direct from g_z3
// ---------------------------------------------------------------------------
__global__ void __launch_bounds__(128)
pass4_lite() {
    unsigned gid = blockIdx.x * blockDim.x + threadIdx.x;
    if (gid >= (unsigned)NDRVN * BB) return;
    int d = gid >> 5;
    int b = gid & 31;

    float v[DD];
    #pragma unroll
    for (int k = 0; k < DD; k++)
        v[k] = __ldg(&g_z3[(d * DD + k) * BB + b]);
    g_zf[d * BB + b] = conv_stack_c(v);
}

// ---------------------------------------------------------------------------
__global__ void zero_kernel(float4* __restrict__ out, int n4) {
    int i = blockIdx.x * blockDim.x + threadIdx.x;
    if (i < n4) out[i] = make_float4(0.f, 0.f, 0.f, 0.f);
}

// ---------------------------------------------------------------------------
// Masked softmax over driver columns; reads g_zf [500][B]
// ---------------------------------------------------------------------------
__global__ void softmax_kernel(const int* __restrict__ drivers,
                               float* __restrict__ out) {
    __shared__ float red[512];
    int b = blockIdx.x;
    int t = threadIdx.x;

    float myv = 0.0f;
    int drv = -1;
    float mval = -INFINITY;
    if (t < NDRVN) {
        drv = drivers[t];
        myv = g_zf[t * BB + b];
        mval = myv;
    }
    red[t] = mval;
    __syncthreads();
    #pragma unroll
    for (int s = 256; s > 0; s >>= 1) {
        if (t < s) red[t] = fmaxf(red[t], red[t + s]);
        __syncthreads();
    }
    float m = fmaxf(red[0], 0.0f);
    __syncthreads();

    float e = (t < NDRVN) ? expf(myv - m) : 0.0f;
    red[t] = e;
    __syncthreads();
    #pragma unroll
    for (int s = 256; s > 0; s >>= 1) {
        if (t < s) red[t] += red[t + s];
        __syncthreads();
    }
    float Z = red[0] + (float)(NNODES - NDRVN) * expf(-m);

    if (t < NDRVN) out[b * NNODES + drv] = e / Z;
}

// ---------------------------------------------------------------------------
extern "C" void kernel_launch(void* const* d_in, const int* in_sizes, int n_in,
                              void* d_out, int out_size) {
    const float* x       = (const float*)d_in[0];
    const int*   nbr     = (const int*)  d_in[1];
    const int*   drivers = (const int*)  d_in[2];
    const float* w_first = (const float*)d_in[4];
    const float* b_first = (const float*)d_in[5];
    const float* w_mid   = (const float*)d_in[6];
    const float* b_mid   = (const float*)d_in[7];
    const float* w_last  = (const float*)d_in[8];
    const float* b_last  = (const float*)d_in[9];
    float* out = (float*)d_out;

    // Copy weights into __constant__ (graph-capturable D2D memcpy nodes)
    cudaMemcpyToSymbolAsync(c_wf, w_first, FEAT * 3 * sizeof(float), 0, cudaMemcpyDeviceToDevice);
    cudaMemcpyToSymbolAsync(c_bf, b_first, FEAT * sizeof(float), 0, cudaMemcpyDeviceToDevice);
    cudaMemcpyToSymbolAsync(c_wm, w_mid, NMID * FEAT * FEAT * 3 * sizeof(float), 0, cudaMemcpyDeviceToDevice);
    cudaMemcpyToSymbolAsync(c_bm, b_mid, NMID * FEAT * sizeof(float), 0, cudaMemcpyDeviceToDevice);
    cudaMemcpyToSymbolAsync(c_wl, w_last, FEAT * 3 * sizeof(float), 0, cudaMemcpyDeviceToDevice);
    cudaMemcpyToSymbolAsync(c_bl, b_last, sizeof(float), 0, cudaMemcpyDeviceToDevice);

    // zero d_out (independent)
    int n4 = NNODES * BB / 4;
    zero_kernel<<<(n4 + 255) / 256, 256>>>((float4*)out, n4);

    transpose_kernel<<<(NNODES + 31) / 32, dim3(32, 32)>>>(x);

    const int blk = 128;
    const int grid_sc = (NNODES * BB + blk - 1) / blk;

    // Passes 1-2: full graph, constant-weight body.  zA -> zB -> zA
    pass_const<0><<<grid_sc, blk>>>(nbr);
    pass_const<1><<<grid_sc, blk>>>(nbr);

    // Pass 3: drivers' neighbors only
    const int grid3 = (NDRVN * DD * BB + blk - 1) / blk;
    pass3_lite<<<grid3, blk>>>(nbr, drivers);

    // Pass 4: drivers only
    const int grid4 = (NDRVN * BB + blk - 1) / blk;
    pass4_lite<<<grid4, blk>>>();

    softmax_kernel<<<BB, 512>>>(drivers, out);
}